// round 9
// baseline (speedup 1.0000x reference)
#include <cuda_runtime.h>
#include <cuda_bf16.h>
#include <cfloat>
#include <cstdint>

// Problem constants
#define TOK   8192
#define DIM   7168
#define NEXP  256
#define TOPKG 4
#define TOPK  8
#define RSCALE 2.5f

// GEMM tiling
#define BM 128
#define BN 128
#define BK 32
#define NCH (DIM / BK)          // 224 K-chunks
#define ROWB 80                 // bytes per smem panel row: 32 bf16 + 16B pad
#define PANELB (128 * ROWB)     // 10240 B
#define STAGEB (6 * PANELB)     // A0,A1,A2,B0,B1,B2 = 61440 B
#define NSTAGE 3
#define SMEM_BYTES (NSTAGE * STAGEB)   // 184320 B

#define NX4 ((size_t)TOK * DIM / 4)    // float4 count of X
#define NW4 ((size_t)NEXP * DIM / 4)

// scratch: bias-added sigmoid scores + precomputed bf16 3-way splits
__device__ float g_scores[(size_t)TOK * NEXP];
__device__ uint2 g_xs[3][NX4];          // each uint2 = 4 bf16
__device__ uint2 g_ws[3][NW4];

// ---------------------------------------------------------------------------
// helpers
// ---------------------------------------------------------------------------
__device__ __forceinline__ uint32_t smem_u32(const void* p) {
    uint32_t a;
    asm("{ .reg .u64 t; cvta.to.shared.u64 t, %1; cvt.u32.u64 %0, t; }"
        : "=r"(a) : "l"(p));
    return a;
}
__device__ __forceinline__ void ldsm_x4(uint32_t* r, uint32_t addr) {
    asm volatile("ldmatrix.sync.aligned.m8n8.x4.shared.b16 {%0,%1,%2,%3}, [%4];"
                 : "=r"(r[0]), "=r"(r[1]), "=r"(r[2]), "=r"(r[3]) : "r"(addr));
}
__device__ __forceinline__ void mma_bf16(float* c, const uint32_t* a, const uint32_t* b) {
    asm volatile(
        "mma.sync.aligned.m16n8k16.row.col.f32.bf16.bf16.f32 "
        "{%0,%1,%2,%3}, {%4,%5,%6,%7}, {%8,%9}, {%0,%1,%2,%3};"
        : "+f"(c[0]), "+f"(c[1]), "+f"(c[2]), "+f"(c[3])
        : "r"(a[0]), "r"(a[1]), "r"(a[2]), "r"(a[3]), "r"(b[0]), "r"(b[1]));
}
__device__ __forceinline__ void cp_async16(uint32_t saddr, const void* g) {
    asm volatile("cp.async.cg.shared.global [%0], [%1], 16;"
                 :: "r"(saddr), "l"(g) : "memory");
}
#define CP_COMMIT() asm volatile("cp.async.commit_group;" ::: "memory")
#define CP_WAIT1()  asm volatile("cp.async.wait_group 1;" ::: "memory")

__device__ __forceinline__ uint32_t b2u(__nv_bfloat162 x) {
    return *reinterpret_cast<uint32_t*>(&x);
}
// exact 3-way bf16 split of a float4 (b0+b1+b2 == x to 2^-25)
__device__ __forceinline__ void split3(float4 v, uint2& o0, uint2& o1, uint2& o2) {
    __nv_bfloat162 p0 = __floats2bfloat162_rn(v.x, v.y);
    __nv_bfloat162 p1 = __floats2bfloat162_rn(v.z, v.w);
    float2 u0 = __bfloat1622float2(p0), u1 = __bfloat1622float2(p1);
    float4 r = make_float4(v.x - u0.x, v.y - u0.y, v.z - u1.x, v.w - u1.y);
    __nv_bfloat162 q0 = __floats2bfloat162_rn(r.x, r.y);
    __nv_bfloat162 q1 = __floats2bfloat162_rn(r.z, r.w);
    float2 w0 = __bfloat1622float2(q0), w1 = __bfloat1622float2(q1);
    __nv_bfloat162 s0 = __floats2bfloat162_rn(r.x - w0.x, r.y - w0.y);
    __nv_bfloat162 s1 = __floats2bfloat162_rn(r.z - w1.x, r.w - w1.y);
    o0 = make_uint2(b2u(p0), b2u(p1));
    o1 = make_uint2(b2u(q0), b2u(q1));
    o2 = make_uint2(b2u(s0), b2u(s1));
}

// ---------------------------------------------------------------------------
// Kernel 0: precompute bf16 3-way splits of X and W (memory-bound)
// ---------------------------------------------------------------------------
__global__ __launch_bounds__(256)
void split_kernel(const float* __restrict__ X, const float* __restrict__ W)
{
    size_t i = (size_t)blockIdx.x * 256 + threadIdx.x;
    if (i < NX4) {
        float4 v = reinterpret_cast<const float4*>(X)[i];
        uint2 a, b, c;
        split3(v, a, b, c);
        g_xs[0][i] = a; g_xs[1][i] = b; g_xs[2][i] = c;
    } else {
        size_t j = i - NX4;
        if (j < NW4) {
            float4 v = reinterpret_cast<const float4*>(W)[j];
            uint2 a, b, c;
            split3(v, a, b, c);
            g_ws[0][j] = a; g_ws[1][j] = b; g_ws[2][j] = c;
        }
    }
}

// ---------------------------------------------------------------------------
// Kernel 1: bf16 6-term GEMM (mma.sync m16n8k16) over precomputed splits.
// Pure cp.async -> ldmatrix -> mma hot loop; per-chunk RN containment.
// 256 threads, warps 2(M) x 4(N), warp tile 64x32, per-warp 4x4 mma tiles.
// ---------------------------------------------------------------------------
__global__ __launch_bounds__(256, 1)
void gemm_mma_kernel(const float* __restrict__ bias, float* __restrict__ S)
{
    extern __shared__ char sm[];
    const int tid  = threadIdx.x;
    const int wid  = tid >> 5, lane = tid & 31;
    const int g    = lane >> 2, tig = lane & 3;
    const int wm   = wid >> 2,  wn  = wid & 3;
    const int m0   = blockIdx.y * BM;
    const int n0   = blockIdx.x * BN;
    const uint32_t sb = smem_u32(sm);

    // ldmatrix per-thread base offsets (within a panel)
    const int t8 = lane >> 3;
    const int r8 = lane & 7;
    const uint32_t a_base =
        (uint32_t)((wm * 64 + (t8 & 1) * 8 + r8) * ROWB + (t8 >> 1) * 16);
    const uint32_t b_base =
        (uint32_t)((wn * 32 + (t8 >> 1) * 8 + r8) * ROWB + (t8 & 1) * 16);

    float acc[4][4][4];
#pragma unroll
    for (int i = 0; i < 4; i++)
#pragma unroll
        for (int j = 0; j < 4; j++)
#pragma unroll
            for (int k = 0; k < 4; k++) acc[i][j][k] = 0.f;

    // prefetch one K chunk (6 bf16 panels) into stage s: 12 cp.async/thread
    auto prefetch = [&](int c, int s) {
        const int k0 = c * BK;
        const uint32_t st = sb + s * STAGEB;
#pragma unroll
        for (int i = 0; i < 2; i++) {
            const int l   = tid + i * 256;       // 0..511
            const int row = l >> 2, q = l & 3;
            const uint32_t d_off = (uint32_t)(row * ROWB + q * 16);
#pragma unroll
            for (int p = 0; p < 3; p++) {
                cp_async16(st + p * PANELB + d_off,
                           (const __nv_bfloat16*)g_xs[p] +
                               (size_t)(m0 + row) * DIM + k0 + q * 8);
                cp_async16(st + (3 + p) * PANELB + d_off,
                           (const __nv_bfloat16*)g_ws[p] +
                               (size_t)(n0 + row) * DIM + k0 + q * 8);
            }
        }
    };

    // prologue
    prefetch(0, 0); CP_COMMIT();
    prefetch(1, 1); CP_COMMIT();

    for (int c = 0; c < NCH; c++) {
        CP_WAIT1();                  // chunk c landed
        __syncthreads();             // and stage (c+2)%3 consumers are done
        if (c + 2 < NCH) prefetch(c + 2, (c + 2) % NSTAGE);
        CP_COMMIT();                 // (possibly empty) keep FIFO indexing

        const uint32_t stage = sb + (c % NSTAGE) * STAGEB;
        const uint32_t apan = stage;
        const uint32_t bpan = stage + 3 * PANELB;

        // warp tile in two M-halves; local acc zeroed per chunk (RN containment)
#pragma unroll
        for (int half = 0; half < 2; half++) {
            float la[2][4][4];
#pragma unroll
            for (int a = 0; a < 2; a++)
#pragma unroll
                for (int b = 0; b < 4; b++)
#pragma unroll
                    for (int k = 0; k < 4; k++) la[a][b][k] = 0.f;

#pragma unroll
            for (int ks = 0; ks < 2; ks++) {
                const uint32_t ko = (uint32_t)(ks * 32);
                uint32_t Bf[3][2][4];
#pragma unroll
                for (int j = 0; j < 3; j++)
#pragma unroll
                    for (int p = 0; p < 2; p++)
                        ldsm_x4(Bf[j][p],
                                bpan + (uint32_t)j * PANELB + b_base + p * (16 * ROWB) + ko);

#pragma unroll
                for (int i = 0; i < 3; i++) {
                    uint32_t Af[2][4];
#pragma unroll
                    for (int mtl = 0; mtl < 2; mtl++)
                        ldsm_x4(Af[mtl],
                                apan + (uint32_t)i * PANELB + a_base +
                                (half * 2 + mtl) * (16 * ROWB) + ko);
#pragma unroll
                    for (int j = 0; j < 3; j++) {
                        if (i + j <= 2) {
#pragma unroll
                            for (int mtl = 0; mtl < 2; mtl++)
#pragma unroll
                                for (int nt = 0; nt < 4; nt++)
                                    mma_bf16(la[mtl][nt], Af[mtl],
                                             &Bf[j][nt >> 1][(nt & 1) * 2]);
                        }
                    }
                }
            }
#pragma unroll
            for (int mtl = 0; mtl < 2; mtl++)
#pragma unroll
                for (int nt = 0; nt < 4; nt++)
#pragma unroll
                    for (int k = 0; k < 4; k++)
                        acc[half * 2 + mtl][nt][k] += la[mtl][nt][k];
        }
    }

    // ---- epilogue: sigmoid + bias -> S
#pragma unroll
    for (int mt = 0; mt < 4; mt++) {
        const int row0 = m0 + wm * 64 + mt * 16 + g;
#pragma unroll
        for (int nt = 0; nt < 4; nt++) {
            const int ncol = n0 + wn * 32 + nt * 8 + tig * 2;
            const float b0 = bias[ncol], b1 = bias[ncol + 1];
            float2 v0, v1;
            v0.x = 1.0f / (1.0f + expf(-acc[mt][nt][0])) + b0;
            v0.y = 1.0f / (1.0f + expf(-acc[mt][nt][1])) + b1;
            v1.x = 1.0f / (1.0f + expf(-acc[mt][nt][2])) + b0;
            v1.y = 1.0f / (1.0f + expf(-acc[mt][nt][3])) + b1;
            *reinterpret_cast<float2*>(S + (size_t)row0 * NEXP + ncol) = v0;
            *reinterpret_cast<float2*>(S + (size_t)(row0 + 8) * NEXP + ncol) = v1;
        }
    }
}

// ---------------------------------------------------------------------------
// Kernel 2: per-token gating (unchanged)
// ---------------------------------------------------------------------------
__global__ __launch_bounds__(256)
void gate_topk_kernel(const float* __restrict__ S,
                      float* __restrict__ outW,
                      float* __restrict__ outI)
{
    const unsigned FULL = 0xffffffffu;
    const int warp = threadIdx.x >> 5;
    const int lane = threadIdx.x & 31;
    const int token = blockIdx.x * 8 + warp;
    if (token >= TOK) return;

    float v[8];
    {
        const float4* p = reinterpret_cast<const float4*>(
            S + (size_t)token * NEXP + lane * 8);
        float4 a = p[0], b = p[1];
        v[0]=a.x; v[1]=a.y; v[2]=a.z; v[3]=a.w;
        v[4]=b.x; v[5]=b.y; v[6]=b.z; v[7]=b.w;
    }

    float m1 = -FLT_MAX, m2 = -FLT_MAX;
#pragma unroll
    for (int j = 0; j < 8; j++) {
        float x = v[j];
        if (x > m1) { m2 = m1; m1 = x; }
        else if (x > m2) { m2 = x; }
    }
#pragma unroll
    for (int off = 2; off >= 1; off >>= 1) {
        float o1 = __shfl_down_sync(FULL, m1, off, 4);
        float o2 = __shfl_down_sync(FULL, m2, off, 4);
        float n1 = fmaxf(m1, o1);
        float n2 = fmaxf(fminf(m1, o1), fmaxf(m2, o2));
        m1 = n1; m2 = n2;
    }
    float gscore = m1 + m2;

    const int myg = lane >> 2;
    float mygs = __shfl_sync(FULL, gscore, myg * 4);
    int rank = 0;
#pragma unroll
    for (int g = 0; g < 8; g++) {
        float gs = __shfl_sync(FULL, gscore, g * 4);
        if (gs > mygs || (gs == mygs && g < myg)) rank++;
    }
    bool sel = (rank < TOPKG);

    float w[8];
#pragma unroll
    for (int j = 0; j < 8; j++) w[j] = sel ? v[j] : 0.0f;

    for (int r = 0; r < TOPK; r++) {
        float bv = w[0]; int bi = lane * 8;
#pragma unroll
        for (int j = 1; j < 8; j++) {
            int idx = lane * 8 + j;
            if (w[j] > bv) { bv = w[j]; bi = idx; }
        }
#pragma unroll
        for (int o = 16; o > 0; o >>= 1) {
            float ov = __shfl_xor_sync(FULL, bv, o);
            int   oi = __shfl_xor_sync(FULL, bi, o);
            if (ov > bv || (ov == bv && oi < bi)) { bv = ov; bi = oi; }
        }
        int owner = bi >> 3;
        float orig = 0.f;
        if (lane == owner) {
            orig = v[bi & 7];
            w[bi & 7] = -FLT_MAX;
        }
        orig = __shfl_sync(FULL, orig, owner);
        if (lane == r) {
            outW[(size_t)token * TOPK + r] = orig * RSCALE;
            outI[(size_t)token * TOPK + r] = (float)bi;
        }
    }
}

// ---------------------------------------------------------------------------
extern "C" void kernel_launch(void* const* d_in, const int* in_sizes, int n_in,
                              void* d_out, int out_size)
{
    const float* x    = (const float*)d_in[0];
    const float* wght = (const float*)d_in[1];
    const float* bias = (const float*)d_in[2];
    float* out = (float*)d_out;

    float* scores;
    cudaGetSymbolAddress((void**)&scores, g_scores);

    cudaFuncSetAttribute(gemm_mma_kernel,
                         cudaFuncAttributeMaxDynamicSharedMemorySize, SMEM_BYTES);

    const size_t total4 = NX4 + NW4;
    const int sgrid = (int)((total4 + 255) / 256);
    split_kernel<<<sgrid, 256>>>(x, wght);

    dim3 grid(NEXP / BN, TOK / BM);
    gemm_mma_kernel<<<grid, 256, SMEM_BYTES>>>(bias, scores);

    gate_topk_kernel<<<TOK / 8, 256>>>(scores, out, out + (size_t)TOK * TOPK);
}

// round 11
// speedup vs baseline: 1.1597x; 1.1597x over previous
#include <cuda_runtime.h>
#include <cuda_bf16.h>
#include <cfloat>
#include <cstdint>

// Problem constants
#define TOK   8192
#define DIM   7168
#define NEXP  256
#define TOPKG 4
#define TOPK  8
#define RSCALE 2.5f

// GEMM tiling
#define BM 128
#define BN 128
#define BK 32
#define NCH (DIM / BK)          // 224 K-chunks
#define NTHREADS 512            // 16 warps: 4(M) x 4(N), warp tile 32x32
#define ROWB 80                 // bytes per smem panel row: 32 bf16 + 16B pad
#define PANELB (128 * ROWB)     // 10240 B
#define STAGEB (6 * PANELB)     // A0,A1,A2,B0,B1,B2 = 61440 B
#define NSTAGE 3
#define SMEM_BYTES (NSTAGE * STAGEB)   // 184320 B

#define NW4 ((size_t)NEXP * DIM / 4)

// scratch: bias-added sigmoid scores + precomputed W bf16 3-way splits
__device__ float g_scores[(size_t)TOK * NEXP];
__device__ uint2 g_ws[3][NW4];          // each uint2 = 4 bf16

// ---------------------------------------------------------------------------
// helpers
// ---------------------------------------------------------------------------
__device__ __forceinline__ uint32_t smem_u32(const void* p) {
    uint32_t a;
    asm("{ .reg .u64 t; cvta.to.shared.u64 t, %1; cvt.u32.u64 %0, t; }"
        : "=r"(a) : "l"(p));
    return a;
}
__device__ __forceinline__ void ldsm_x4(uint32_t* r, uint32_t addr) {
    asm volatile("ldmatrix.sync.aligned.m8n8.x4.shared.b16 {%0,%1,%2,%3}, [%4];"
                 : "=r"(r[0]), "=r"(r[1]), "=r"(r[2]), "=r"(r[3]) : "r"(addr));
}
__device__ __forceinline__ void mma_bf16(float* c, const uint32_t* a, const uint32_t* b) {
    asm volatile(
        "mma.sync.aligned.m16n8k16.row.col.f32.bf16.bf16.f32 "
        "{%0,%1,%2,%3}, {%4,%5,%6,%7}, {%8,%9}, {%0,%1,%2,%3};"
        : "+f"(c[0]), "+f"(c[1]), "+f"(c[2]), "+f"(c[3])
        : "r"(a[0]), "r"(a[1]), "r"(a[2]), "r"(a[3]), "r"(b[0]), "r"(b[1]));
}
__device__ __forceinline__ void cp_async16(uint32_t saddr, const void* g) {
    asm volatile("cp.async.cg.shared.global [%0], [%1], 16;"
                 :: "r"(saddr), "l"(g) : "memory");
}
#define CP_COMMIT() asm volatile("cp.async.commit_group;" ::: "memory")
#define CP_WAIT1()  asm volatile("cp.async.wait_group 1;" ::: "memory")

__device__ __forceinline__ uint32_t b2u(__nv_bfloat162 x) {
    return *reinterpret_cast<uint32_t*>(&x);
}
// exact 3-way bf16 split of a float4 (b0+b1+b2 == x to 2^-25)
__device__ __forceinline__ void split3(float4 v, uint2& o0, uint2& o1, uint2& o2) {
    __nv_bfloat162 p0 = __floats2bfloat162_rn(v.x, v.y);
    __nv_bfloat162 p1 = __floats2bfloat162_rn(v.z, v.w);
    float2 u0 = __bfloat1622float2(p0), u1 = __bfloat1622float2(p1);
    float4 r = make_float4(v.x - u0.x, v.y - u0.y, v.z - u1.x, v.w - u1.y);
    __nv_bfloat162 q0 = __floats2bfloat162_rn(r.x, r.y);
    __nv_bfloat162 q1 = __floats2bfloat162_rn(r.z, r.w);
    float2 w0 = __bfloat1622float2(q0), w1 = __bfloat1622float2(q1);
    __nv_bfloat162 s0 = __floats2bfloat162_rn(r.x - w0.x, r.y - w0.y);
    __nv_bfloat162 s1 = __floats2bfloat162_rn(r.z - w1.x, r.w - w1.y);
    o0 = make_uint2(b2u(p0), b2u(p1));
    o1 = make_uint2(b2u(q0), b2u(q1));
    o2 = make_uint2(b2u(s0), b2u(s1));
}

// ---------------------------------------------------------------------------
// Kernel 0: precompute W bf16 3-way splits (11 MB -> L2-resident in GEMM)
// ---------------------------------------------------------------------------
__global__ __launch_bounds__(256)
void splitw_kernel(const float* __restrict__ W)
{
    size_t i = (size_t)blockIdx.x * 256 + threadIdx.x;
    if (i < NW4) {
        float4 v = reinterpret_cast<const float4*>(W)[i];
        uint2 a, b, c;
        split3(v, a, b, c);
        g_ws[0][i] = a; g_ws[1][i] = b; g_ws[2][i] = c;
    }
}

// ---------------------------------------------------------------------------
// Kernel 1: bf16 6-term GEMM. A split in-loop (regs->smem), B via cp.async
// from precomputed splits. Per-chunk RN containment. 512 threads, 16 warps.
// ---------------------------------------------------------------------------
__global__ __launch_bounds__(NTHREADS, 1)
void gemm_mma_kernel(const float* __restrict__ X,
                     const float* __restrict__ bias,
                     float* __restrict__ S)
{
    extern __shared__ char sm[];
    const int tid  = threadIdx.x;
    const int wid  = tid >> 5, lane = tid & 31;
    const int g    = lane >> 2, tig = lane & 3;
    const int wm   = wid >> 2,  wn  = wid & 3;     // 4x4 warp grid
    const int m0   = blockIdx.y * BM;
    const int n0   = blockIdx.x * BN;
    const uint32_t sb = smem_u32(sm);

    // ldmatrix per-thread base offsets (within a panel)
    const int t8 = lane >> 3;
    const int r8 = lane & 7;
    const uint32_t a_base =
        (uint32_t)((wm * 32 + (t8 & 1) * 8 + r8) * ROWB + (t8 >> 1) * 16);
    const uint32_t b_base =
        (uint32_t)((wn * 32 + (t8 >> 1) * 8 + r8) * ROWB + (t8 & 1) * 16);

    // A producer coords: element e = tid -> row e>>3, float4 q=e&7
    const int pr = tid >> 3, pq = tid & 7;
    const uint32_t pa_off = (uint32_t)(pr * ROWB + pq * 8);
    // B producer coords: 3 cp.async per thread
    const int br = tid >> 2, bq = tid & 3;
    const uint32_t pb_off = (uint32_t)(br * ROWB + bq * 16);

    float acc[2][4][4];
#pragma unroll
    for (int i = 0; i < 2; i++)
#pragma unroll
        for (int j = 0; j < 4; j++)
#pragma unroll
            for (int k = 0; k < 4; k++) acc[i][j][k] = 0.f;

    float4 R[2];   // A LDG buffer (rows pr, pr+64)

    auto ldg_a = [&](int c) {
        const int k0 = c * BK;
        R[0] = *reinterpret_cast<const float4*>(
            X + (size_t)(m0 + pr) * DIM + k0 + pq * 4);
        R[1] = *reinterpret_cast<const float4*>(
            X + (size_t)(m0 + pr + 64) * DIM + k0 + pq * 4);
    };
    auto sts_a = [&](int s) {
        char* ab = sm + s * STAGEB;
#pragma unroll
        for (int i = 0; i < 2; i++) {
            uint2 o0, o1, o2;
            split3(R[i], o0, o1, o2);
            const uint32_t off = pa_off + (uint32_t)(64 * i) * ROWB;
            *reinterpret_cast<uint2*>(ab + off)              = o0;
            *reinterpret_cast<uint2*>(ab + PANELB + off)     = o1;
            *reinterpret_cast<uint2*>(ab + 2 * PANELB + off) = o2;
        }
    };
    auto cpb = [&](int c, int s) {
        const int k0 = c * BK;
        const uint32_t st = sb + s * STAGEB + 3 * PANELB;
#pragma unroll
        for (int p = 0; p < 3; p++)
            cp_async16(st + p * PANELB + pb_off,
                       (const __nv_bfloat16*)g_ws[p] +
                           (size_t)(n0 + br) * DIM + k0 + bq * 8);
    };

    // prologue
    ldg_a(0);
    sts_a(0);
    ldg_a(1);
    cpb(0, 0); CP_COMMIT();
    cpb(1, 1); CP_COMMIT();

    for (int c = 0; c < NCH; c++) {
        CP_WAIT1();                  // B chunk c landed
        __syncthreads();             // A stores for c visible; old stages free
        if (c + 1 < NCH) sts_a((c + 1) % NSTAGE);
        if (c + 2 < NCH) { ldg_a(c + 2); cpb(c + 2, (c + 2) % NSTAGE); }
        CP_COMMIT();                 // keep FIFO group indexing

        const uint32_t stage = sb + (c % NSTAGE) * STAGEB;
        const uint32_t apan = stage;
        const uint32_t bpan = stage + 3 * PANELB;

        float la[2][4][4];
#pragma unroll
        for (int a = 0; a < 2; a++)
#pragma unroll
            for (int b = 0; b < 4; b++)
#pragma unroll
                for (int k = 0; k < 4; k++) la[a][b][k] = 0.f;

#pragma unroll
        for (int ks = 0; ks < 2; ks++) {
            const uint32_t ko = (uint32_t)(ks * 32);
            uint32_t Bf[3][2][4];
#pragma unroll
            for (int j = 0; j < 3; j++)
#pragma unroll
                for (int p = 0; p < 2; p++)
                    ldsm_x4(Bf[j][p],
                            bpan + (uint32_t)j * PANELB + b_base + p * (16 * ROWB) + ko);

#pragma unroll
            for (int i = 0; i < 3; i++) {
                uint32_t Af[2][4];
#pragma unroll
                for (int mt = 0; mt < 2; mt++)
                    ldsm_x4(Af[mt],
                            apan + (uint32_t)i * PANELB + a_base + mt * (16 * ROWB) + ko);
#pragma unroll
                for (int j = 0; j < 3; j++) {
                    if (i + j <= 2) {
#pragma unroll
                        for (int mt = 0; mt < 2; mt++)
#pragma unroll
                            for (int nt = 0; nt < 4; nt++)
                                mma_bf16(la[mt][nt], Af[mt],
                                         &Bf[j][nt >> 1][(nt & 1) * 2]);
                    }
                }
            }
        }
        // RN fold (containment of TC rounding)
#pragma unroll
        for (int mt = 0; mt < 2; mt++)
#pragma unroll
            for (int nt = 0; nt < 4; nt++)
#pragma unroll
                for (int k = 0; k < 4; k++)
                    acc[mt][nt][k] += la[mt][nt][k];
    }

    // ---- epilogue: sigmoid + bias -> S
#pragma unroll
    for (int mt = 0; mt < 2; mt++) {
        const int row0 = m0 + wm * 32 + mt * 16 + g;
#pragma unroll
        for (int nt = 0; nt < 4; nt++) {
            const int ncol = n0 + wn * 32 + nt * 8 + tig * 2;
            const float b0 = bias[ncol], b1 = bias[ncol + 1];
            float2 v0, v1;
            v0.x = 1.0f / (1.0f + expf(-acc[mt][nt][0])) + b0;
            v0.y = 1.0f / (1.0f + expf(-acc[mt][nt][1])) + b1;
            v1.x = 1.0f / (1.0f + expf(-acc[mt][nt][2])) + b0;
            v1.y = 1.0f / (1.0f + expf(-acc[mt][nt][3])) + b1;
            *reinterpret_cast<float2*>(S + (size_t)row0 * NEXP + ncol) = v0;
            *reinterpret_cast<float2*>(S + (size_t)(row0 + 8) * NEXP + ncol) = v1;
        }
    }
}

// ---------------------------------------------------------------------------
// Kernel 2: per-token gating (unchanged)
// ---------------------------------------------------------------------------
__global__ __launch_bounds__(256)
void gate_topk_kernel(const float* __restrict__ S,
                      float* __restrict__ outW,
                      float* __restrict__ outI)
{
    const unsigned FULL = 0xffffffffu;
    const int warp = threadIdx.x >> 5;
    const int lane = threadIdx.x & 31;
    const int token = blockIdx.x * 8 + warp;
    if (token >= TOK) return;

    float v[8];
    {
        const float4* p = reinterpret_cast<const float4*>(
            S + (size_t)token * NEXP + lane * 8);
        float4 a = p[0], b = p[1];
        v[0]=a.x; v[1]=a.y; v[2]=a.z; v[3]=a.w;
        v[4]=b.x; v[5]=b.y; v[6]=b.z; v[7]=b.w;
    }

    float m1 = -FLT_MAX, m2 = -FLT_MAX;
#pragma unroll
    for (int j = 0; j < 8; j++) {
        float x = v[j];
        if (x > m1) { m2 = m1; m1 = x; }
        else if (x > m2) { m2 = x; }
    }
#pragma unroll
    for (int off = 2; off >= 1; off >>= 1) {
        float o1 = __shfl_down_sync(FULL, m1, off, 4);
        float o2 = __shfl_down_sync(FULL, m2, off, 4);
        float n1 = fmaxf(m1, o1);
        float n2 = fmaxf(fminf(m1, o1), fmaxf(m2, o2));
        m1 = n1; m2 = n2;
    }
    float gscore = m1 + m2;

    const int myg = lane >> 2;
    float mygs = __shfl_sync(FULL, gscore, myg * 4);
    int rank = 0;
#pragma unroll
    for (int g = 0; g < 8; g++) {
        float gs = __shfl_sync(FULL, gscore, g * 4);
        if (gs > mygs || (gs == mygs && g < myg)) rank++;
    }
    bool sel = (rank < TOPKG);

    float w[8];
#pragma unroll
    for (int j = 0; j < 8; j++) w[j] = sel ? v[j] : 0.0f;

    for (int r = 0; r < TOPK; r++) {
        float bv = w[0]; int bi = lane * 8;
#pragma unroll
        for (int j = 1; j < 8; j++) {
            int idx = lane * 8 + j;
            if (w[j] > bv) { bv = w[j]; bi = idx; }
        }
#pragma unroll
        for (int o = 16; o > 0; o >>= 1) {
            float ov = __shfl_xor_sync(FULL, bv, o);
            int   oi = __shfl_xor_sync(FULL, bi, o);
            if (ov > bv || (ov == bv && oi < bi)) { bv = ov; bi = oi; }
        }
        int owner = bi >> 3;
        float orig = 0.f;
        if (lane == owner) {
            orig = v[bi & 7];
            w[bi & 7] = -FLT_MAX;
        }
        orig = __shfl_sync(FULL, orig, owner);
        if (lane == r) {
            outW[(size_t)token * TOPK + r] = orig * RSCALE;
            outI[(size_t)token * TOPK + r] = (float)bi;
        }
    }
}

// ---------------------------------------------------------------------------
extern "C" void kernel_launch(void* const* d_in, const int* in_sizes, int n_in,
                              void* d_out, int out_size)
{
    const float* x    = (const float*)d_in[0];
    const float* wght = (const float*)d_in[1];
    const float* bias = (const float*)d_in[2];
    float* out = (float*)d_out;

    float* scores;
    cudaGetSymbolAddress((void**)&scores, g_scores);

    cudaFuncSetAttribute(gemm_mma_kernel,
                         cudaFuncAttributeMaxDynamicSharedMemorySize, SMEM_BYTES);

    splitw_kernel<<<(int)((NW4 + 255) / 256), 256>>>(wght);

    dim3 grid(NEXP / BN, TOK / BM);
    gemm_mma_kernel<<<grid, NTHREADS, SMEM_BYTES>>>(x, bias, scores);

    gate_topk_kernel<<<TOK / 8, 256>>>(scores, out, out + (size_t)TOK * TOPK);
}